// round 16
// baseline (speedup 1.0000x reference)
#include <cuda_runtime.h>

#define TT 512
#define BB 64
#define II 512
#define HH 512

// rnn_persist smem layout (per CTA)
#define HS2 258     // float2 (=8B) stride per batch row of h
#define RP8 260     // ull stride per k-plane in reduction (256 used)
#define RED_OFF (8 * HS2 * 8)                  // 16512
#define SMEM_TOTAL (RED_OFF + 8 * RP8 * 8)     // 33152

// Static device scratch (no allocations allowed)
__device__ float g_xp[2][TT][BB][HH];      // input projections per direction
__device__ float g_h[2][2][BB][HH];        // [dir][buf][b][h] double-buffered state
__device__ unsigned g_flag[2][8][16][32];  // [dir][bgroup][nslice] flags, 128B padded

typedef unsigned long long ull;

__device__ __forceinline__ void fma2(ull& acc, ull a, ull b) {
    asm("fma.rn.f32x2 %0, %1, %2, %0;" : "+l"(acc) : "l"(a), "l"(b));
}
__device__ __forceinline__ ull add2(ull a, ull b) {
    ull r; asm("add.rn.f32x2 %0, %1, %2;" : "=l"(r) : "l"(a), "l"(b)); return r;
}
__device__ __forceinline__ float2 unpack2(ull v) {
    float2 r; asm("mov.b64 {%0, %1}, %2;" : "=f"(r.x), "=f"(r.y) : "l"(v)); return r;
}
__device__ __forceinline__ unsigned ld_acq(const unsigned* p) {
    unsigned v; asm volatile("ld.acquire.gpu.u32 %0, [%1];" : "=r"(v) : "l"(p) : "memory");
    return v;
}
__device__ __forceinline__ void st_rel(unsigned* p, unsigned v) {
    asm volatile("st.release.gpu.u32 [%0], %1;" :: "l"(p), "r"(v) : "memory");
}

// ---------------------------------------------------------------------------
// Phase 1: xp[dir][t][b][n] = sum_i x[b][t][i] * W[n][i] + bias[n]
// (proven scalar FFMA2 version, unchanged)
// ---------------------------------------------------------------------------
__global__ __launch_bounds__(256) void xproj_kernel(
    const float* __restrict__ x,
    const float* __restrict__ Wf, const float* __restrict__ bf,
    const float* __restrict__ Wb, const float* __restrict__ bbias) {
    const int dir = blockIdx.z;
    const float* __restrict__ W    = dir ? Wb : Wf;
    const float* __restrict__ bias = dir ? bbias : bf;
    const int t = blockIdx.y;
    const int n_base = blockIdx.x * 64;

    __shared__ float2 a2[8][66];   // [k2][m]
    __shared__ float2 b2[8][66];   // [k2][n]

    const int tid = threadIdx.x;
    const int w = tid >> 5, lane = tid & 31;
    const int mgrp = ((w >> 1) << 2) | (lane >> 3);  // 0..15
    const int ngrp = ((w & 1) << 3) | (lane & 7);    // 0..15
    const int m0 = mgrp << 2, n0l = ngrp << 2;

    const int lr = tid >> 2;
    const int lq = (tid & 3) << 2;
    const float* arow = x + ((size_t)lr * TT + t) * II + lq;
    const float* brow = W + (size_t)(n_base + lr) * II + lq;

    ull acc[4][4];
#pragma unroll
    for (int i = 0; i < 4; i++)
#pragma unroll
        for (int j = 0; j < 4; j++) acc[i][j] = 0ull;

    for (int st = 0; st < 32; st++) {
        float4 pa = *(const float4*)(arow + st * 16);
        float4 pb = *(const float4*)(brow + st * 16);
        __syncthreads();
        a2[(lq >> 1) + 0][lr] = make_float2(pa.x, pa.y);
        a2[(lq >> 1) + 1][lr] = make_float2(pa.z, pa.w);
        b2[(lq >> 1) + 0][lr] = make_float2(pb.x, pb.y);
        b2[(lq >> 1) + 1][lr] = make_float2(pb.z, pb.w);
        __syncthreads();
#pragma unroll
        for (int k2 = 0; k2 < 8; k2++) {
            ulonglong2 av0 = *(const ulonglong2*)&a2[k2][m0];
            ulonglong2 av1 = *(const ulonglong2*)&a2[k2][m0 + 2];
            ulonglong2 bv0 = *(const ulonglong2*)&b2[k2][n0l];
            ulonglong2 bv1 = *(const ulonglong2*)&b2[k2][n0l + 2];
            ull am[4] = {av0.x, av0.y, av1.x, av1.y};
            ull bn[4] = {bv0.x, bv0.y, bv1.x, bv1.y};
#pragma unroll
            for (int i = 0; i < 4; i++)
#pragma unroll
                for (int j = 0; j < 4; j++)
                    fma2(acc[i][j], am[i], bn[j]);
        }
    }

    float4 bv = *(const float4*)(bias + n_base + n0l);
#pragma unroll
    for (int i = 0; i < 4; i++) {
        float2 s0 = unpack2(acc[i][0]);
        float2 s1 = unpack2(acc[i][1]);
        float2 s2 = unpack2(acc[i][2]);
        float2 s3 = unpack2(acc[i][3]);
        float4 v;
        v.x = s0.x + s0.y + bv.x;
        v.y = s1.x + s1.y + bv.y;
        v.z = s2.x + s2.y + bv.z;
        v.w = s3.x + s3.y + bv.w;
        *(float4*)&g_xp[dir][t][m0 + i][n_base + n0l] = v;
    }
}

// ---------------------------------------------------------------------------
// Phase 2: persistent recurrence. 256 CTAs x 256 threads, 2 CTAs/SM
// (independent sync domains: dir = bid>>7 pairs fwd+bwd per SM).
// Per dir: 8 b-groups x 16 n-slices; CTA tile 8b x 32n.
// Warp = k-slice (32 k2); lane = n-col; weights in registers (w[32]).
// h broadcast LDS.128; 8-plane reduce; 16-CTA flag barrier per b-group.
// ---------------------------------------------------------------------------
__global__ __launch_bounds__(256, 2) void rnn_persist(
    const float* __restrict__ Whf, const float* __restrict__ Whb,
    const float* __restrict__ h0f, const float* __restrict__ h0b,
    float* __restrict__ out) {
    extern __shared__ char smem[];
    float2* hs = (float2*)smem;                 // [8][HS2]
    ull* red   = (ull*)(smem + RED_OFF);        // [8][RP8]

    const int bid = blockIdx.x;
    const int dir = bid >> 7;               // 0..1 (bids k, k+128 pair per SM)
    const int rest = bid & 127;
    const int bg = rest >> 4;               // b-group 0..7
    const int ns = rest & 15;               // n-slice 0..15
    const int b_base = 8 * bg;
    const int n_base = 32 * ns;
    const float* __restrict__ Wh = dir ? Whb : Whf;
    const float* __restrict__ h0 = dir ? h0b : h0f;
    const int tid = threadIdx.x;
    const int wid = tid >> 5;               // warp = k-slice 0..7 (32 k2 each)
    const int lane = tid & 31;
    const int n0 = n_base + lane;           // this thread's n column

    // ---- one-time weight fill into REGISTERS: w[kk] = {W[n0][2k2], W[n0][2k2+1]}
    ull w[32];
#pragma unroll
    for (int kk = 0; kk < 32; kk++) {
        int k2 = 32 * wid + kk;
        w[kk] = *(const ull*)(Wh + (size_t)n0 * HH + 2 * k2);
    }

    // reducer: output o = tid -> (b_local = tid>>5, n_local = tid&31)
    const int rbl = tid >> 5;
    const int rnl = tid & 31;
    const int rn = n_base + rnl;

    const unsigned base = ld_acq(&g_flag[dir][bg][ns][0]);
    const ulonglong2* hwarp2 = (const ulonglong2*)((const ull*)hs + 32 * wid);

    for (int s = 0; s < TT; s++) {
        const int t = dir ? (TT - 1 - s) : s;
        const float* __restrict__ hin =
            (s == 0) ? h0 : (const float*)g_h[dir][s & 1];
        float* __restrict__ hout = (float*)g_h[dir][(s & 1) ^ 1];

        // ---- stage 8 x 512 h into hs (1024 float4, 4 per thread) ----
#pragma unroll
        for (int i = 0; i < 4; i++) {
            int idx = tid + 256 * i;
            int b = idx >> 7, c = idx & 127;
            float4 v = *(const float4*)(hin + (size_t)(b_base + b) * HH + 4 * c);
            *(float4*)&hs[b * HS2 + 2 * c] = v;
        }
        float xpv = g_xp[dir][t][b_base + rbl][rn];
        __syncthreads();

        // ---- mainloop: 1n x 8b; w in regs; h broadcast LDS.128 (2 k2) ----
        ull acc[8];
#pragma unroll
        for (int i = 0; i < 8; i++) acc[i] = 0ull;
#pragma unroll
        for (int kk2 = 0; kk2 < 16; kk2++) {
            ulonglong2 ha = hwarp2[(0 * HS2) / 2 + kk2];
            ulonglong2 hb = hwarp2[(1 * HS2) / 2 + kk2];
            ulonglong2 hc = hwarp2[(2 * HS2) / 2 + kk2];
            ulonglong2 hd = hwarp2[(3 * HS2) / 2 + kk2];
            ulonglong2 he = hwarp2[(4 * HS2) / 2 + kk2];
            ulonglong2 hf = hwarp2[(5 * HS2) / 2 + kk2];
            ulonglong2 hg = hwarp2[(6 * HS2) / 2 + kk2];
            ulonglong2 hh = hwarp2[(7 * HS2) / 2 + kk2];
            ull w0 = w[2 * kk2], w1 = w[2 * kk2 + 1];
            fma2(acc[0], ha.x, w0); fma2(acc[0], ha.y, w1);
            fma2(acc[1], hb.x, w0); fma2(acc[1], hb.y, w1);
            fma2(acc[2], hc.x, w0); fma2(acc[2], hc.y, w1);
            fma2(acc[3], hd.x, w0); fma2(acc[3], hd.y, w1);
            fma2(acc[4], he.x, w0); fma2(acc[4], he.y, w1);
            fma2(acc[5], hf.x, w0); fma2(acc[5], hf.y, w1);
            fma2(acc[6], hg.x, w0); fma2(acc[6], hg.y, w1);
            fma2(acc[7], hh.x, w0); fma2(acc[7], hh.y, w1);
        }

        // ---- partials: red[wid][b*32 + lane] ----
        {
            ull* rp = red + (size_t)wid * RP8 + lane;
#pragma unroll
            for (int b = 0; b < 8; b++)
                rp[b * 32] = acc[b];
        }
        __syncthreads();

        // ---- 8-way reduce (1 output/thread) + tanh ----
        ull ssum = red[tid];
#pragma unroll
        for (int k = 1; k < 8; k++) ssum = add2(ssum, red[k * RP8 + tid]);
        float2 f = unpack2(ssum);
        float v = tanhf(f.x + f.y + xpv);
        const int rb = b_base + rbl;

        if (s < TT - 1) {
            hout[(size_t)rb * HH + rn] = v;
            __syncthreads();                 // all hout writes issued
            if (tid == 0) st_rel(&g_flag[dir][bg][ns][0], base + s + 1);
            // y store off the inter-CTA critical path
            out[((size_t)rb * TT + t) * (2 * HH) + (size_t)dir * HH + rn] = v;
            // poll the 16 flags of this b-group
            if (tid < 16) {
                const unsigned tgt = base + (unsigned)(s + 1);
                const unsigned* f16 = &g_flag[dir][bg][tid][0];
                while (ld_acq(f16) < tgt) {}
            }
            __syncthreads();
        } else {
            out[((size_t)rb * TT + t) * (2 * HH) + (size_t)dir * HH + rn] = v;
            float* hT = out + (size_t)BB * TT * 2 * HH + (size_t)dir * BB * HH;
            hT[(size_t)rb * HH + rn] = v;
        }
    }
}

extern "C" void kernel_launch(void* const* d_in, const int* in_sizes, int n_in,
                              void* d_out, int out_size) {
    const float* x     = (const float*)d_in[0];
    const float* h0f   = (const float*)d_in[1];
    const float* h0b   = (const float*)d_in[2];
    const float* Wxf_w = (const float*)d_in[3];
    const float* Wxf_b = (const float*)d_in[4];
    const float* Whf_w = (const float*)d_in[5];
    const float* Wxb_w = (const float*)d_in[6];
    const float* Wxb_b = (const float*)d_in[7];
    const float* Whb_w = (const float*)d_in[8];
    float* out = (float*)d_out;

    static int smem_set = 0;
    if (!smem_set) {
        cudaFuncSetAttribute(rnn_persist,
                             cudaFuncAttributeMaxDynamicSharedMemorySize,
                             SMEM_TOTAL);
        smem_set = 1;
    }

    xproj_kernel<<<dim3(HH / 64, TT, 2), 256>>>(x, Wxf_w, Wxf_b, Wxb_w, Wxb_b);
    rnn_persist<<<256, 256, SMEM_TOTAL>>>(Whf_w, Whb_w, h0f, h0b, out);
}